// round 1
// baseline (speedup 1.0000x reference)
#include <cuda_runtime.h>
#include <cuda_bf16.h>

#define N_SEL   8192
#define N_FEAT  256
#define K_SUB   256
#define N_PERS  4
#define E_FULL  262144
#define E_RAW   262144
#define N_TOTAL 8192
#define EPSILON 0.5f
#define LAMB1   0.5f

// ---------------- device scratch (no allocations allowed) ----------------
__device__ float        g_wsq[N_PERS * N_FEAT];     // metric_weight^2
__device__ float        g_rinv[N_PERS * N_SEL];     // 1/(||x_n ∘ w_p|| + 1e-12)
__device__ float        g_score[K_SUB];             // normalized subgraph scores
__device__ float        g_nodew[N_SEL];             // score[batch[i]] * LAMB1
__device__ unsigned int g_bitmap[(size_t)N_SEL * N_SEL / 32];  // 8 MB edge-dedup bitmap

// ---------------- fill / clear ----------------
__global__ void zero_out_kernel(float4* __restrict__ out) {
    int i = blockIdx.x * blockDim.x + threadIdx.x;   // exactly covers 16777216 float4
    out[i] = make_float4(0.f, 0.f, 0.f, 0.f);
}

__global__ void clear_bitmap_kernel() {
    int i = blockIdx.x * blockDim.x + threadIdx.x;   // exactly covers 524288 uint4
    reinterpret_cast<uint4*>(g_bitmap)[i] = make_uint4(0u, 0u, 0u, 0u);
}

// ---------------- tiny preps ----------------
__global__ void prep_wsq_kernel(const float* __restrict__ w) {
    int i = blockIdx.x * blockDim.x + threadIdx.x;
    if (i < N_PERS * N_FEAT) {
        float v = w[i];
        g_wsq[i] = v * v;
    }
}

// single block of 256 threads; deterministic segment sum (K_SUB x K_SUB scan)
__global__ void prep_score_kernel(const float* __restrict__ sc,
                                  const int* __restrict__ belong) {
    __shared__ float s_sc[K_SUB];
    __shared__ int   s_bl[K_SUB];
    __shared__ float s_sum[K_SUB];
    int t = threadIdx.x;
    s_sc[t] = sc[t];
    s_bl[t] = belong[t];
    __syncthreads();
    float s = 0.f;
    #pragma unroll 8
    for (int k = 0; k < K_SUB; k++)
        s += (s_bl[k] == t) ? s_sc[k] : 0.f;
    s_sum[t] = s;
    __syncthreads();
    g_score[t] = s_sc[t] / s_sum[s_bl[t]];
}

__global__ void prep_nodew_kernel(const int* __restrict__ batch) {
    int i = blockIdx.x * blockDim.x + threadIdx.x;
    if (i < N_SEL) g_nodew[i] = g_score[batch[i]] * LAMB1;
}

// one warp per node: 4 weighted squared-norms
__global__ void prep_rinv_kernel(const float* __restrict__ x) {
    __shared__ float swsq[N_PERS * N_FEAT];
    for (int i = threadIdx.x; i < N_PERS * N_FEAT; i += blockDim.x)
        swsq[i] = g_wsq[i];
    __syncthreads();

    int n    = (blockIdx.x * blockDim.x + threadIdx.x) >> 5;
    int lane = threadIdx.x & 31;
    if (n >= N_SEL) return;

    const float4* xr = reinterpret_cast<const float4*>(x + (size_t)n * N_FEAT);
    float4 a0 = xr[lane];        // dims [4*lane, 4*lane+4)
    float4 a1 = xr[lane + 32];   // dims [128+4*lane, ...)
    int d0 = lane * 4, d1 = 128 + lane * 4;

    float s0 = a0.x * a0.x, s1 = a0.y * a0.y, s2 = a0.z * a0.z, s3 = a0.w * a0.w;
    float s4 = a1.x * a1.x, s5 = a1.y * a1.y, s6 = a1.z * a1.z, s7 = a1.w * a1.w;

    float acc[N_PERS];
    #pragma unroll
    for (int p = 0; p < N_PERS; p++) {
        const float* wq = swsq + p * N_FEAT;
        acc[p] = s0 * wq[d0]     + s1 * wq[d0 + 1] + s2 * wq[d0 + 2] + s3 * wq[d0 + 3]
               + s4 * wq[d1]     + s5 * wq[d1 + 1] + s6 * wq[d1 + 2] + s7 * wq[d1 + 3];
    }
    #pragma unroll
    for (int p = 0; p < N_PERS; p++)
        #pragma unroll
        for (int o = 16; o > 0; o >>= 1)
            acc[p] += __shfl_xor_sync(0xffffffffu, acc[p], o);

    if (lane == 0) {
        #pragma unroll
        for (int p = 0; p < N_PERS; p++)
            g_rinv[p * N_SEL + n] = 1.0f / (sqrtf(acc[p]) + 1e-12f);
    }
}

// ---------------- main edge kernel: one warp per full edge ----------------
__global__ void edge_kernel(const float* __restrict__ x,
                            const int* __restrict__ fe,
                            const int* __restrict__ smap,
                            float* __restrict__ out) {
    __shared__ float swsq[N_PERS * N_FEAT];
    for (int i = threadIdx.x; i < N_PERS * N_FEAT; i += blockDim.x)
        swsq[i] = g_wsq[i];
    __syncthreads();

    int e    = (blockIdx.x * blockDim.x + threadIdx.x) >> 5;
    int lane = threadIdx.x & 31;
    if (e >= E_FULL) return;

    int i = __ldg(fe + e);
    int j = __ldg(fe + E_FULL + e);
    if (i == j) return;                     // diagonal is zeroed in reference

    // dedup: mask was built with .set(1.0) — each distinct (i,j) counts once
    int owner = 0;
    if (lane == 0) {
        size_t idx = (size_t)i * N_SEL + j;
        unsigned bit = 1u << (idx & 31u);
        unsigned old = atomicOr(&g_bitmap[idx >> 5], bit);
        owner = (old & bit) ? 0 : 1;
    }
    owner = __shfl_sync(0xffffffffu, owner, 0);
    if (!owner) return;

    const float4* xi = reinterpret_cast<const float4*>(x + (size_t)i * N_FEAT);
    const float4* xj = reinterpret_cast<const float4*>(x + (size_t)j * N_FEAT);
    float4 a0 = xi[lane], a1 = xi[lane + 32];
    float4 b0 = xj[lane], b1 = xj[lane + 32];

    float p0 = a0.x * b0.x, p1 = a0.y * b0.y, p2 = a0.z * b0.z, p3 = a0.w * b0.w;
    float p4 = a1.x * b1.x, p5 = a1.y * b1.y, p6 = a1.z * b1.z, p7 = a1.w * b1.w;
    int d0 = lane * 4, d1 = 128 + lane * 4;

    float acc[N_PERS];
    #pragma unroll
    for (int p = 0; p < N_PERS; p++) {
        const float* wq = swsq + p * N_FEAT;
        acc[p] = p0 * wq[d0]     + p1 * wq[d0 + 1] + p2 * wq[d0 + 2] + p3 * wq[d0 + 3]
               + p4 * wq[d1]     + p5 * wq[d1 + 1] + p6 * wq[d1 + 2] + p7 * wq[d1 + 3];
    }
    #pragma unroll
    for (int p = 0; p < N_PERS; p++)
        #pragma unroll
        for (int o = 16; o > 0; o >>= 1)
            acc[p] += __shfl_xor_sync(0xffffffffu, acc[p], o);

    if (lane == 0) {
        float sim = 0.25f * (acc[0] * g_rinv[i]             * g_rinv[j]
                           + acc[1] * g_rinv[N_SEL + i]     * g_rinv[N_SEL + j]
                           + acc[2] * g_rinv[2 * N_SEL + i] * g_rinv[2 * N_SEL + j]
                           + acc[3] * g_rinv[3 * N_SEL + i] * g_rinv[3 * N_SEL + j]);
        if (sim > EPSILON) {
            atomicAdd(out + (size_t)__ldg(smap + i) * N_TOTAL + __ldg(smap + j),
                      sim * g_nodew[i]);
        }
    }
}

// ---------------- raw graph edges: out[r0, r1] += (1 - lamb1) ----------------
__global__ void raw_kernel(const int* __restrict__ re, float* __restrict__ out) {
    int e = blockIdx.x * blockDim.x + threadIdx.x;
    if (e < E_RAW) {
        int r = __ldg(re + e);
        int c = __ldg(re + E_RAW + e);
        atomicAdd(out + (size_t)r * N_TOTAL + c, 1.0f - LAMB1);
    }
}

// ---------------- launch ----------------
extern "C" void kernel_launch(void* const* d_in, const int* in_sizes, int n_in,
                              void* d_out, int out_size) {
    const float* x      = (const float*)d_in[0];   // [8192, 256]
    const float* mw     = (const float*)d_in[1];   // [4, 256]
    const int*   batch  = (const int*)  d_in[2];   // [8192]
    const int*   smap   = (const int*)  d_in[3];   // [8192]
    const int*   belong = (const int*)  d_in[4];   // [256]
    const float* score  = (const float*)d_in[5];   // [256]
    const int*   fe     = (const int*)  d_in[6];   // [2, 262144]
    const int*   re     = (const int*)  d_in[7];   // [2, 262144]
    float* out = (float*)d_out;                    // [8192, 8192]

    // zero 256 MB output (poisoned by harness) : 16777216 float4
    zero_out_kernel<<<65536, 256>>>(reinterpret_cast<float4*>(out));
    // clear 8 MB dedup bitmap : 524288 uint4
    clear_bitmap_kernel<<<2048, 256>>>();

    prep_wsq_kernel<<<4, 256>>>(mw);
    prep_score_kernel<<<1, 256>>>(score, belong);
    prep_nodew_kernel<<<32, 256>>>(batch);
    prep_rinv_kernel<<<1024, 256>>>(x);            // 8192 warps, 1/node

    edge_kernel<<<E_FULL / 8, 256>>>(x, fe, smap, out);  // 1 warp / edge
    raw_kernel<<<E_RAW / 256, 256>>>(re, out);
}

// round 2
// speedup vs baseline: 1.3281x; 1.3281x over previous
#include <cuda_runtime.h>
#include <cuda_bf16.h>

#define N_SEL   8192
#define N_FEAT  256
#define K_SUB   256
#define N_PERS  4
#define E_FULL  262144
#define E_RAW   262144
#define N_TOTAL 8192
#define EPSILON 0.5f
#define LAMB1   0.5f

// ---------------- device scratch (no allocations allowed) ----------------
__device__ float4       g_rinv4[N_SEL];             // per-node {rinv_p0..p3}
__device__ float        g_score[K_SUB];             // normalized subgraph scores
__device__ float        g_nodew[N_SEL];             // score[batch[i]] * LAMB1
__device__ unsigned int g_bitmap[(size_t)N_SEL * N_SEL / 32];  // 8 MB edge-dedup bitmap

// ---------------- fused fill: zero 256 MB output + clear 8 MB bitmap ----------------
// grid covers exactly 16777216 (out float4) + 524288 (bitmap uint4) = 17301504 slots
__global__ void fill_kernel(float4* __restrict__ out) {
    int i = blockIdx.x * blockDim.x + threadIdx.x;
    if (i < 16777216) {
        out[i] = make_float4(0.f, 0.f, 0.f, 0.f);
    } else {
        reinterpret_cast<uint4*>(g_bitmap)[i - 16777216] = make_uint4(0u, 0u, 0u, 0u);
    }
}

// ---------------- score normalization + per-node weight (1 block) ----------------
__global__ void prep_score_kernel(const float* __restrict__ sc,
                                  const int* __restrict__ belong,
                                  const int* __restrict__ batch) {
    __shared__ float s_sc[K_SUB];
    __shared__ int   s_bl[K_SUB];
    __shared__ float s_sum[K_SUB];
    __shared__ float s_norm[K_SUB];
    int t = threadIdx.x;
    s_sc[t] = sc[t];
    s_bl[t] = belong[t];
    __syncthreads();
    float s = 0.f;
    #pragma unroll 8
    for (int k = 0; k < K_SUB; k++)
        s += (s_bl[k] == t) ? s_sc[k] : 0.f;
    s_sum[t] = s;
    __syncthreads();
    float ns = s_sc[t] / s_sum[s_bl[t]];
    g_score[t] = ns;
    s_norm[t] = ns;
    __syncthreads();
    // per-node weight: 8192 nodes with 256 threads
    for (int i = t; i < N_SEL; i += K_SUB)
        g_nodew[i] = s_norm[batch[i]] * LAMB1;
}

// ---------------- per-node inverse weighted norms (warp per node) ----------------
__global__ void __launch_bounds__(256) prep_rinv_kernel(const float* __restrict__ x,
                                                        const float* __restrict__ mw) {
    int lane = threadIdx.x & 31;
    // squared weights, lane-local slice, in registers
    const float4* mw4 = reinterpret_cast<const float4*>(mw);
    float4 w0[N_PERS], w1[N_PERS];
    #pragma unroll
    for (int p = 0; p < N_PERS; p++) {
        float4 a = __ldg(mw4 + p * 64 + lane);
        float4 b = __ldg(mw4 + p * 64 + 32 + lane);
        w0[p] = make_float4(a.x * a.x, a.y * a.y, a.z * a.z, a.w * a.w);
        w1[p] = make_float4(b.x * b.x, b.y * b.y, b.z * b.z, b.w * b.w);
    }

    int n = (blockIdx.x * blockDim.x + threadIdx.x) >> 5;
    if (n >= N_SEL) return;

    const float4* xr = reinterpret_cast<const float4*>(x + (size_t)n * N_FEAT);
    float4 a0 = __ldg(xr + lane);
    float4 a1 = __ldg(xr + lane + 32);
    float s0 = a0.x * a0.x, s1 = a0.y * a0.y, s2 = a0.z * a0.z, s3 = a0.w * a0.w;
    float s4 = a1.x * a1.x, s5 = a1.y * a1.y, s6 = a1.z * a1.z, s7 = a1.w * a1.w;

    float acc[N_PERS];
    #pragma unroll
    for (int p = 0; p < N_PERS; p++)
        acc[p] = s0 * w0[p].x + s1 * w0[p].y + s2 * w0[p].z + s3 * w0[p].w
               + s4 * w1[p].x + s5 * w1[p].y + s6 * w1[p].z + s7 * w1[p].w;
    #pragma unroll
    for (int p = 0; p < N_PERS; p++)
        #pragma unroll
        for (int o = 16; o > 0; o >>= 1)
            acc[p] += __shfl_xor_sync(0xffffffffu, acc[p], o);

    if (lane == 0) {
        g_rinv4[n] = make_float4(1.0f / (sqrtf(acc[0]) + 1e-12f),
                                 1.0f / (sqrtf(acc[1]) + 1e-12f),
                                 1.0f / (sqrtf(acc[2]) + 1e-12f),
                                 1.0f / (sqrtf(acc[3]) + 1e-12f));
    }
}

// ---------------- main edge kernel: persistent warps, weights in registers ----------------
__global__ void __launch_bounds__(256) edge_kernel(const float* __restrict__ x,
                                                   const float* __restrict__ mw,
                                                   const int* __restrict__ fe,
                                                   const int* __restrict__ smap,
                                                   const int* __restrict__ re,
                                                   float* __restrict__ out) {
    int lane = threadIdx.x & 31;
    const float4* mw4 = reinterpret_cast<const float4*>(mw);
    float4 w0[N_PERS], w1[N_PERS];
    #pragma unroll
    for (int p = 0; p < N_PERS; p++) {
        float4 a = __ldg(mw4 + p * 64 + lane);
        float4 b = __ldg(mw4 + p * 64 + 32 + lane);
        w0[p] = make_float4(a.x * a.x, a.y * a.y, a.z * a.z, a.w * a.w);
        w1[p] = make_float4(b.x * b.x, b.y * b.y, b.z * b.z, b.w * b.w);
    }

    int warp_id = (blockIdx.x * blockDim.x + threadIdx.x) >> 5;
    int n_warps = (gridDim.x * blockDim.x) >> 5;

    for (int e = warp_id; e < E_FULL; e += n_warps) {
        int i = __ldg(fe + e);
        int j = __ldg(fe + E_FULL + e);
        if (i == j) continue;                     // diagonal zeroed in reference

        const float4* xi = reinterpret_cast<const float4*>(x + (size_t)i * N_FEAT);
        const float4* xj = reinterpret_cast<const float4*>(x + (size_t)j * N_FEAT);
        float4 a0 = __ldg(xi + lane), a1 = __ldg(xi + lane + 32);
        float4 b0 = __ldg(xj + lane), b1 = __ldg(xj + lane + 32);

        float p0 = a0.x * b0.x, p1 = a0.y * b0.y, p2 = a0.z * b0.z, p3 = a0.w * b0.w;
        float p4 = a1.x * b1.x, p5 = a1.y * b1.y, p6 = a1.z * b1.z, p7 = a1.w * b1.w;

        float acc[N_PERS];
        #pragma unroll
        for (int p = 0; p < N_PERS; p++)
            acc[p] = p0 * w0[p].x + p1 * w0[p].y + p2 * w0[p].z + p3 * w0[p].w
                   + p4 * w1[p].x + p5 * w1[p].y + p6 * w1[p].z + p7 * w1[p].w;
        #pragma unroll
        for (int p = 0; p < N_PERS; p++)
            #pragma unroll
            for (int o = 16; o > 0; o >>= 1)
                acc[p] += __shfl_xor_sync(0xffffffffu, acc[p], o);

        if (lane == 0) {
            float4 ri = g_rinv4[i];
            float4 rj = g_rinv4[j];
            float sim = 0.25f * (acc[0] * ri.x * rj.x + acc[1] * ri.y * rj.y
                               + acc[2] * ri.z * rj.z + acc[3] * ri.w * rj.w);
            if (sim > EPSILON) {
                // rare path: dedup (mask built with .set → distinct (i,j) counts once)
                size_t idx = (size_t)i * N_SEL + j;
                unsigned bit = 1u << (idx & 31u);
                unsigned old = atomicOr(&g_bitmap[idx >> 5], bit);
                if (!(old & bit)) {
                    atomicAdd(out + (size_t)__ldg(smap + i) * N_TOTAL + __ldg(smap + j),
                              sim * g_nodew[i]);
                }
            }
        }
    }

    // -------- raw graph edges folded in: out[r0, r1] += (1 - lamb1) --------
    int tid = blockIdx.x * blockDim.x + threadIdx.x;
    int n_thr = gridDim.x * blockDim.x;
    for (int e = tid; e < E_RAW; e += n_thr) {
        int r = __ldg(re + e);
        int c = __ldg(re + E_RAW + e);
        atomicAdd(out + (size_t)r * N_TOTAL + c, 1.0f - LAMB1);
    }
}

// ---------------- launch ----------------
extern "C" void kernel_launch(void* const* d_in, const int* in_sizes, int n_in,
                              void* d_out, int out_size) {
    const float* x      = (const float*)d_in[0];   // [8192, 256]
    const float* mw     = (const float*)d_in[1];   // [4, 256]
    const int*   batch  = (const int*)  d_in[2];   // [8192]
    const int*   smap   = (const int*)  d_in[3];   // [8192]
    const int*   belong = (const int*)  d_in[4];   // [256]
    const float* score  = (const float*)d_in[5];   // [256]
    const int*   fe     = (const int*)  d_in[6];   // [2, 262144]
    const int*   re     = (const int*)  d_in[7];   // [2, 262144]
    float* out = (float*)d_out;                    // [8192, 8192]

    prep_score_kernel<<<1, 256>>>(score, belong, batch);
    prep_rinv_kernel<<<1024, 256>>>(x, mw);                 // 8192 warps, 1/node
    fill_kernel<<<67584, 256>>>(reinterpret_cast<float4*>(out));  // out + bitmap
    edge_kernel<<<1184, 256>>>(x, mw, fe, smap, re, out);   // persistent, 8 blocks/SM
}